// round 14
// baseline (speedup 1.0000x reference)
#include <cuda_runtime.h>
#include <cuda_bf16.h>
#include <math.h>
#include <stdint.h>

#define TT 96
#define NN 1024
#define GG 128
#define HH 512
#define EE 32768
#define INW 64
#define DD2 56

typedef unsigned long long ull;

// ---------------- scratch (static __device__, no allocs) ----------------
__device__ float d_bufA[TT * NN * GG];   // gemm outputs
__device__ float d_bufB[TT * NN * GG];   // mp outputs
__device__ int   d_cnt[TT * NN];
__device__ int   d_offs[TT * NN];
__device__ int   d_cursor[TT * NN];
__device__ float d_dinv[TT * NN];
__device__ int   d_csr[TT * EE];
__device__ float d_gacc[TT * DD2];
__device__ float d_pre[TT * 4 * HH];
__device__ float d_hbuf[2 * HH];
__device__ float d_cbuf[HH];
__device__ unsigned d_bar;
__device__ int   d_eistride;
// W1 split to bf16 hi/lo, packed per 32-K chunk as [kc][n][kk] (n=0..127, kk=0..31)
__device__ __nv_bfloat16 d_W1h[NN * GG];
__device__ __nv_bfloat16 d_W1l[NN * GG];

// ---------------- f32x2 helpers (packed fp32 FMA pipe) ----------------
__device__ __forceinline__ ull f32x2_fma(ull a, ull b, ull c) {
    ull d;
    asm("fma.rn.f32x2 %0, %1, %2, %3;" : "=l"(d) : "l"(a), "l"(b), "l"(c));
    return d;
}
__device__ __forceinline__ ull f32x2_dup(float x) {
    ull d;
    asm("mov.b64 %0, {%1, %1};" : "=l"(d) : "f"(x));
    return d;
}
__device__ __forceinline__ float2 f32x2_unpack(ull v) {
    float2 r;
    asm("mov.b64 {%0, %1}, %2;" : "=f"(r.x), "=f"(r.y) : "l"(v));
    return r;
}

// ---------------- mma.sync bf16 (baseline PTX, HMMA path) -----------------
__device__ __forceinline__ void mma16816(float* d, const uint32_t* a,
                                         uint32_t b0, uint32_t b1) {
    asm volatile(
        "mma.sync.aligned.m16n8k16.row.col.f32.bf16.bf16.f32 "
        "{%0,%1,%2,%3}, {%4,%5,%6,%7}, {%8,%9}, {%0,%1,%2,%3};"
        : "+f"(d[0]), "+f"(d[1]), "+f"(d[2]), "+f"(d[3])
        : "r"(a[0]), "r"(a[1]), "r"(a[2]), "r"(a[3]), "r"(b0), "r"(b1));
}

// ---------------- edge_index dtype detection ------------------------------
__global__ void k_detect(const int* __restrict__ ei32) {
    __shared__ int any;
    if (threadIdx.x == 0) any = 0;
    __syncthreads();
    int v = ei32[2 * threadIdx.x + 1] | ei32[2 * (threadIdx.x + 4096) + 1];
    if (v != 0) atomicOr(&any, 1);
    __syncthreads();
    if (threadIdx.x == 0) d_eistride = any ? 1 : 2;
}

// ---------------- init ----------------
__global__ void k_init() {
    int i = blockIdx.x * blockDim.x + threadIdx.x;
    if (i < TT * NN) d_cnt[i] = 0;
    if (i < TT * DD2) d_gacc[i] = 0.f;
    if (i < 2 * HH) d_hbuf[i] = 0.f;
    if (i < HH) d_cbuf[i] = 0.f;
    if (i == 0) d_bar = 0u;
}

// ---------------- W1 -> bf16 hi/lo chunk-packed [kc][n][kk] ---------------
__global__ void k_prepB(const float* __restrict__ W1) {
    int idx = blockIdx.x * blockDim.x + threadIdx.x;   // 1024*128
    if (idx >= NN * GG) return;
    int k = idx >> 7;       // 0..1023
    int n = idx & 127;
    float w = W1[idx];
    __nv_bfloat16 h = __float2bfloat16(w);
    __nv_bfloat16 l = __float2bfloat16(w - __bfloat162float(h));
    int kc = k >> 5, kk = k & 31;
    int off = kc * 4096 + n * 32 + kk;
    d_W1h[off] = h;
    d_W1l[off] = l;
}

// ---------------- GEMM1 via mma.sync bf16-split, reg double-buffered ------
// bufA[t][128-tile] = x_nodes[t] @ W1 ; 8 warps, warp tile 32x64, K chunk 32.
__global__ void __launch_bounds__(256)
k_gemm1_mma(const float* __restrict__ A) {
    __shared__ __nv_bfloat16 sAh[128][36], sAl[128][36];
    __shared__ __nv_bfloat16 sBh[128][36], sBl[128][36];
    int t = blockIdx.y, m0 = blockIdx.x * 128;
    const float* At = A + (size_t)t * NN * NN + (size_t)m0 * NN;
    float* Ct = d_bufA + (size_t)t * NN * GG + (size_t)m0 * GG;
    int tid = threadIdx.x, wid = tid >> 5, lane = tid & 31;
    int wm = (wid >> 1) * 32, wn = (wid & 1) * 64;
    int lr = lane >> 2, lc = (lane & 3) * 2;
    int pm = tid >> 4, pk = tid & 15;        // prefetch coords: row, k-pair

    float acc[2][8][4];
#pragma unroll
    for (int mt = 0; mt < 2; mt++)
#pragma unroll
        for (int nt = 0; nt < 8; nt++)
#pragma unroll
            for (int q = 0; q < 4; q++) acc[mt][nt][q] = 0.f;

    // prefetch registers for next chunk
    float2 pa[8];
    uint32_t pbh[8], pbl[8];
    // preload chunk 0
#pragma unroll
    for (int i = 0; i < 8; i++) {
        int m = pm + i * 16;
        pa[i] = *(const float2*)&At[(size_t)m * NN + pk * 2];
        pbh[i] = ((const uint32_t*)d_W1h)[tid + i * 256];
        pbl[i] = ((const uint32_t*)d_W1l)[tid + i * 256];
    }

#pragma unroll 1
    for (int kc = 0; kc < 32; kc++) {
        __syncthreads();                 // smem consumers of prev chunk done
        // convert+store prefetched A, store B
#pragma unroll
        for (int i = 0; i < 8; i++) {
            int m = pm + i * 16;
            __nv_bfloat16 h0 = __float2bfloat16(pa[i].x);
            __nv_bfloat16 h1 = __float2bfloat16(pa[i].y);
            __nv_bfloat16 l0 = __float2bfloat16(pa[i].x - __bfloat162float(h0));
            __nv_bfloat16 l1 = __float2bfloat16(pa[i].y - __bfloat162float(h1));
            __nv_bfloat162 hh; hh.x = h0; hh.y = h1;
            __nv_bfloat162 ll; ll.x = l0; ll.y = l1;
            *(__nv_bfloat162*)&sAh[m][pk * 2] = hh;
            *(__nv_bfloat162*)&sAl[m][pk * 2] = ll;
            int lin = tid + i * 256;
            int n = lin >> 4, kp = lin & 15;
            *(uint32_t*)&sBh[n][kp * 2] = pbh[i];
            *(uint32_t*)&sBl[n][kp * 2] = pbl[i];
        }
        __syncthreads();                 // smem ready for this chunk

        // issue next-chunk global loads NOW (hidden behind the mma block)
        {
            int kn = (kc + 1) & 31;
#pragma unroll
            for (int i = 0; i < 8; i++) {
                int m = pm + i * 16;
                pa[i] = *(const float2*)&At[(size_t)m * NN + kn * 32 + pk * 2];
                pbh[i] = ((const uint32_t*)d_W1h)[kn * 2048 + tid + i * 256];
                pbl[i] = ((const uint32_t*)d_W1l)[kn * 2048 + tid + i * 256];
            }
        }

#pragma unroll
        for (int ks = 0; ks < 2; ks++) {
            int kb = ks * 16;
            uint32_t ah[2][4], al[2][4];
#pragma unroll
            for (int mt = 0; mt < 2; mt++) {
                int r0 = wm + mt * 16 + lr;
                ah[mt][0] = *(uint32_t*)&sAh[r0][kb + lc];
                ah[mt][1] = *(uint32_t*)&sAh[r0 + 8][kb + lc];
                ah[mt][2] = *(uint32_t*)&sAh[r0][kb + lc + 8];
                ah[mt][3] = *(uint32_t*)&sAh[r0 + 8][kb + lc + 8];
                al[mt][0] = *(uint32_t*)&sAl[r0][kb + lc];
                al[mt][1] = *(uint32_t*)&sAl[r0 + 8][kb + lc];
                al[mt][2] = *(uint32_t*)&sAl[r0][kb + lc + 8];
                al[mt][3] = *(uint32_t*)&sAl[r0 + 8][kb + lc + 8];
            }
#pragma unroll
            for (int nt = 0; nt < 8; nt++) {
                int c0 = wn + nt * 8 + lr;
                uint32_t bh0 = *(uint32_t*)&sBh[c0][kb + lc];
                uint32_t bh1 = *(uint32_t*)&sBh[c0][kb + lc + 8];
                uint32_t bl0 = *(uint32_t*)&sBl[c0][kb + lc];
                uint32_t bl1 = *(uint32_t*)&sBl[c0][kb + lc + 8];
#pragma unroll
                for (int mt = 0; mt < 2; mt++) {
                    mma16816(acc[mt][nt], ah[mt], bh0, bh1);
                    mma16816(acc[mt][nt], ah[mt], bl0, bl1);
                    mma16816(acc[mt][nt], al[mt], bh0, bh1);
                }
            }
        }
    }
#pragma unroll
    for (int mt = 0; mt < 2; mt++)
#pragma unroll
        for (int nt = 0; nt < 8; nt++) {
            int r = wm + mt * 16 + lr;
            int c = wn + nt * 8 + lc;
            Ct[(size_t)r * GG + c]       = acc[mt][nt][0];
            Ct[(size_t)r * GG + c + 1]   = acc[mt][nt][1];
            Ct[(size_t)(r + 8) * GG + c]     = acc[mt][nt][2];
            Ct[(size_t)(r + 8) * GG + c + 1] = acc[mt][nt][3];
        }
}

// ---------------- degree count ----------------
__global__ void k_count(const int* __restrict__ ei32) {
    int idx = blockIdx.x * blockDim.x + threadIdx.x;
    if (idx >= TT * EE) return;
    int t = idx / EE, e = idx - t * EE;
    int st = d_eistride;
    size_t k = (size_t)t * 2 * EE + EE + e;
    int dst = ei32[k * st] & (NN - 1);
    atomicAdd(&d_cnt[t * NN + dst], 1);
}

// ---------------- per-t exclusive scan + dinv ----------------
__global__ void k_scan() {
    __shared__ int s[2][NN];
    int t = blockIdx.x, n = threadIdx.x;
    int c = d_cnt[t * NN + n];
    d_dinv[t * NN + n] = rsqrtf((float)(c + 1));
    s[0][n] = c;
    __syncthreads();
    int p = 0;
    for (int off = 1; off < NN; off <<= 1) {
        int v = s[p][n] + ((n >= off) ? s[p][n - off] : 0);
        s[1 - p][n] = v;
        __syncthreads();
        p = 1 - p;
    }
    int excl = s[p][n] - c;
    d_offs[t * NN + n] = excl;
    d_cursor[t * NN + n] = excl;
}

// ---------------- CSR fill ----------------
__global__ void k_fill(const int* __restrict__ ei32) {
    int idx = blockIdx.x * blockDim.x + threadIdx.x;
    if (idx >= TT * EE) return;
    int t = idx / EE, e = idx - t * EE;
    int st = d_eistride;
    size_t ksrc = (size_t)t * 2 * EE + e;
    size_t kdst = ksrc + EE;
    int src = ei32[ksrc * st] & (NN - 1);
    int dst = ei32[kdst * st] & (NN - 1);
    int pos = atomicAdd(&d_cursor[t * NN + dst], 1);
    d_csr[(size_t)t * EE + pos] = src;
}

// ---------------- SGEMM2 (f32x2): bufA[t] = bufB[t](1024x128) @ W2 --------
__global__ void __launch_bounds__(256)
k_gemm2(const float* __restrict__ B) {
    int t = blockIdx.y;
    int m0 = blockIdx.x * 128;
    const float* At = d_bufB + (size_t)t * NN * GG;
    float* Ct = d_bufA + (size_t)t * NN * GG;

    __shared__ float As[8][128];
    __shared__ float Bs[8][128];

    int tid = threadIdx.x;
    int tx = tid & 15, ty = tid >> 4;
    int am = tid >> 1, ap = (tid & 1) * 4;
    int brow = tid >> 5, bcol = (tid & 31) * 4;

    ull acc[8][4];
#pragma unroll
    for (int r = 0; r < 8; r++)
#pragma unroll
        for (int q = 0; q < 4; q++) acc[r][q] = 0ull;

    for (int k0 = 0; k0 < 128; k0 += 8) {
        float4 av = *(const float4*)&At[(size_t)(m0 + am) * 128 + k0 + ap];
        float4 bv = *(const float4*)&B[(size_t)(k0 + brow) * 128 + bcol];
        __syncthreads();
        As[ap + 0][am] = av.x; As[ap + 1][am] = av.y;
        As[ap + 2][am] = av.z; As[ap + 3][am] = av.w;
        Bs[brow][bcol + 0] = bv.x; Bs[brow][bcol + 1] = bv.y;
        Bs[brow][bcol + 2] = bv.z; Bs[brow][bcol + 3] = bv.w;
        __syncthreads();
#pragma unroll
        for (int kk = 0; kk < 8; kk++) {
            float4 b0 = *(float4*)&Bs[kk][tx * 4];
            float4 b1 = *(float4*)&Bs[kk][64 + tx * 4];
            ull bp0 = ((ull*)&b0)[0], bp1 = ((ull*)&b0)[1];
            ull bp2 = ((ull*)&b1)[0], bp3 = ((ull*)&b1)[1];
            float ar[8];
#pragma unroll
            for (int u = 0; u < 4; u++) {
                ar[u] = As[kk][ty * 4 + u];
                ar[4 + u] = As[kk][64 + ty * 4 + u];
            }
#pragma unroll
            for (int r = 0; r < 8; r++) {
                ull da = f32x2_dup(ar[r]);
                acc[r][0] = f32x2_fma(da, bp0, acc[r][0]);
                acc[r][1] = f32x2_fma(da, bp1, acc[r][1]);
                acc[r][2] = f32x2_fma(da, bp2, acc[r][2]);
                acc[r][3] = f32x2_fma(da, bp3, acc[r][3]);
            }
        }
    }
#pragma unroll
    for (int r = 0; r < 8; r++) {
        int row = m0 + ((r < 4) ? (ty * 4 + r) : (64 + ty * 4 + (r - 4)));
        float2 c0 = f32x2_unpack(acc[r][0]);
        float2 c1 = f32x2_unpack(acc[r][1]);
        float2 c2 = f32x2_unpack(acc[r][2]);
        float2 c3 = f32x2_unpack(acc[r][3]);
        float4 o0 = make_float4(c0.x, c0.y, c1.x, c1.y);
        float4 o1 = make_float4(c2.x, c2.y, c3.x, c3.y);
        *(float4*)&Ct[(size_t)row * GG + tx * 4] = o0;
        *(float4*)&Ct[(size_t)row * GG + 64 + tx * 4] = o1;
    }
}

// ---------------- message passing (CSR gather): bufA -> bufB -------------
__global__ void k_mp(const float* __restrict__ bias, int relu) {
    int t = blockIdx.y, n = blockIdx.x, f = threadIdx.x;
    const float* xwt = d_bufA + (size_t)t * NN * GG;
    float dn = d_dinv[t * NN + n];
    float acc = bias[f] + dn * dn * xwt[(size_t)n * GG + f];
    int s = d_offs[t * NN + n];
    int c = d_cnt[t * NN + n];
    const int* csr = d_csr + (size_t)t * EE + s;

    __shared__ int ssrc[128];
    __shared__ float snrm[128];

    for (int base = 0; base < c; base += 128) {
        int m = c - base; if (m > 128) m = 128;
        __syncthreads();
        if (f < m) {
            int sr = csr[base + f];
            ssrc[f] = sr;
            snrm[f] = dn * d_dinv[t * NN + sr];
        }
        __syncthreads();
        float a0 = 0.f, a1 = 0.f, a2 = 0.f, a3 = 0.f;
        float a4 = 0.f, a5 = 0.f, a6 = 0.f, a7 = 0.f;
        int i = 0;
        for (; i + 8 <= m; i += 8) {
            a0 += snrm[i + 0] * xwt[(size_t)ssrc[i + 0] * GG + f];
            a1 += snrm[i + 1] * xwt[(size_t)ssrc[i + 1] * GG + f];
            a2 += snrm[i + 2] * xwt[(size_t)ssrc[i + 2] * GG + f];
            a3 += snrm[i + 3] * xwt[(size_t)ssrc[i + 3] * GG + f];
            a4 += snrm[i + 4] * xwt[(size_t)ssrc[i + 4] * GG + f];
            a5 += snrm[i + 5] * xwt[(size_t)ssrc[i + 5] * GG + f];
            a6 += snrm[i + 6] * xwt[(size_t)ssrc[i + 6] * GG + f];
            a7 += snrm[i + 7] * xwt[(size_t)ssrc[i + 7] * GG + f];
        }
        for (; i < m; i++)
            a0 += snrm[i] * xwt[(size_t)ssrc[i] * GG + f];
        acc += ((a0 + a1) + (a2 + a3)) + ((a4 + a5) + (a6 + a7));
    }
    if (relu) acc = fmaxf(acc, 0.f);
    d_bufB[(size_t)t * NN * GG + (size_t)n * GG + f] = acc;
}

// ---------------- FC: gacc[t][:] += bufB[t][n][:] @ Wfc[n-chunk] ----------
__global__ void k_fc(const float* __restrict__ Wfc) {
    __shared__ float Ws[128 * DD2];
    __shared__ float xs[128];
    __shared__ float ps[224];
    int n = blockIdx.x;
    int tid = threadIdx.x;
    for (int i = tid; i < 128 * DD2; i += 224)
        Ws[i] = Wfc[(size_t)n * 128 * DD2 + i];
    int dd = tid % DD2, q = tid / DD2;
    for (int t = 0; t < TT; t++) {
        __syncthreads();
        if (tid < 128)
            xs[tid] = d_bufB[(size_t)t * NN * GG + (size_t)n * GG + tid];
        __syncthreads();
        float a = 0.f;
#pragma unroll 8
        for (int k = q * 32; k < q * 32 + 32; k++)
            a += xs[k] * Ws[k * DD2 + dd];
        ps[tid] = a;
        __syncthreads();
        if (q == 0) {
            float ssum = a + ps[56 + dd] + ps[112 + dd] + ps[168 + dd];
            atomicAdd(&d_gacc[t * DD2 + dd], ssum);
        }
    }
}

// ---------------- pre-activations: x@W_i + relu(g)@W_g + b ----------------
__global__ void k_pre(const float* __restrict__ input,
                      const float* __restrict__ bfc,
                      const float* __restrict__ Wii, const float* __restrict__ Wgi, const float* __restrict__ bi,
                      const float* __restrict__ Wif, const float* __restrict__ Wgf, const float* __restrict__ bf,
                      const float* __restrict__ Wig, const float* __restrict__ Wgg, const float* __restrict__ bg,
                      const float* __restrict__ Wio, const float* __restrict__ Wgo, const float* __restrict__ bo) {
    int idx = blockIdx.x * blockDim.x + threadIdx.x;
    if (idx >= TT * 4 * HH) return;
    int t = idx >> 11;
    int r = idx & 2047;
    int gate = r >> 9;
    int hh = r & 511;
    const float* Wi = (gate == 0) ? Wii : (gate == 1) ? Wif : (gate == 2) ? Wig : Wio;
    const float* Wg = (gate == 0) ? Wgi : (gate == 1) ? Wgf : (gate == 2) ? Wgg : Wgo;
    const float* bb = (gate == 0) ? bi : (gate == 1) ? bf : (gate == 2) ? bg : bo;
    const float* x = input + (size_t)t * INW;
    float a = bb[hh];
#pragma unroll 8
    for (int k = 0; k < INW; k++)
        a += x[k] * Wi[(size_t)k * HH + hh];
#pragma unroll 8
    for (int d = 0; d < DD2; d++) {
        float gd = d_gacc[t * DD2 + d] + bfc[d];
        gd = fmaxf(gd, 0.f);
        a += gd * Wg[(size_t)d * HH + hh];
    }
    d_pre[(size_t)t * 2048 + gate * 512 + hh] = a;
}

// ---------------- persistent LSTM recurrence ----------------
#define LSTM_NB 64
__global__ void __launch_bounds__(256, 1)
k_lstm(const float* __restrict__ Whi, const float* __restrict__ Whf,
       const float* __restrict__ Whg, const float* __restrict__ Who,
       float* __restrict__ out) {
    int wid = (blockIdx.x * 256 + threadIdx.x) >> 5;
    int lane = threadIdx.x & 31;
    int j = wid;

    float wi[16], wf[16], wg[16], wo[16];
#pragma unroll
    for (int q = 0; q < 16; q++) {
        int m = lane * 16 + q;
        wi[q] = Whi[(size_t)m * HH + j];
        wf[q] = Whf[(size_t)m * HH + j];
        wg[q] = Whg[(size_t)m * HH + j];
        wo[q] = Who[(size_t)m * HH + j];
    }

    float c = 0.f, h = 0.f;
    for (int t = 0; t < TT; t++) {
        volatile float* hb = d_hbuf + (t & 1) * HH;
        float ai = 0.f, af = 0.f, ag = 0.f, ao = 0.f;
#pragma unroll
        for (int q = 0; q < 16; q++) {
            float hv = hb[lane * 16 + q];
            ai += wi[q] * hv;
            af += wf[q] * hv;
            ag += wg[q] * hv;
            ao += wo[q] * hv;
        }
#pragma unroll
        for (int off = 16; off > 0; off >>= 1) {
            ai += __shfl_xor_sync(0xffffffffu, ai, off);
            af += __shfl_xor_sync(0xffffffffu, af, off);
            ag += __shfl_xor_sync(0xffffffffu, ag, off);
            ao += __shfl_xor_sync(0xffffffffu, ao, off);
        }
        if (lane == 0) {
            const float* p = d_pre + (size_t)t * 2048;
            float xi = p[j] + ai;
            float xf = p[512 + j] + af;
            float xg = p[1024 + j] + ag;
            float xo = p[1536 + j] + ao;
            float ii = 1.f / (1.f + expf(-xi));
            float ff = 1.f / (1.f + expf(-xf));
            float gg = tanhf(xg);
            float oo = 1.f / (1.f + expf(-xo));
            c = ff * c + ii * gg;
            h = oo * tanhf(c);
            d_hbuf[((t + 1) & 1) * HH + j] = h;
            out[(size_t)t * HH + j] = h;
        }
        __threadfence();
        __syncthreads();
        if (threadIdx.x == 0) {
            atomicAdd(&d_bar, 1u);
            unsigned target = (unsigned)LSTM_NB * (unsigned)(t + 1);
            while (*((volatile unsigned*)&d_bar) < target) {}
        }
        __syncthreads();
        __threadfence();
    }
    if (lane == 0) {
        out[(size_t)TT * HH + j] = h;
        out[(size_t)TT * HH + HH + j] = c;
    }
}

// ---------------- launch ----------------
extern "C" void kernel_launch(void* const* d_in, const int* in_sizes, int n_in,
                              void* d_out, int out_size) {
    const float* input    = (const float*)d_in[0];
    const float* x_nodes  = (const float*)d_in[1];
    const int*   ei32     = (const int*)d_in[2];
    const float* W1  = (const float*)d_in[3];
    const float* b1  = (const float*)d_in[4];
    const float* W2  = (const float*)d_in[5];
    const float* b2  = (const float*)d_in[6];
    const float* Wfc = (const float*)d_in[7];
    const float* bfc = (const float*)d_in[8];
    const float* Wii = (const float*)d_in[9];
    const float* Wgi = (const float*)d_in[10];
    const float* Whi = (const float*)d_in[11];
    const float* bi  = (const float*)d_in[12];
    const float* Wif = (const float*)d_in[13];
    const float* Wgf = (const float*)d_in[14];
    const float* Whf = (const float*)d_in[15];
    const float* bf  = (const float*)d_in[16];
    const float* Wig = (const float*)d_in[17];
    const float* Wgg = (const float*)d_in[18];
    const float* Whg = (const float*)d_in[19];
    const float* bg  = (const float*)d_in[20];
    const float* Wio = (const float*)d_in[21];
    const float* Wgo = (const float*)d_in[22];
    const float* Who = (const float*)d_in[23];
    const float* bo  = (const float*)d_in[24];
    float* out = (float*)d_out;

    // order: k_gemm1_mma is the 4th launch (ncu profiling window)
    k_detect<<<1, 256>>>(ei32);
    k_init<<<(TT * NN + 255) / 256, 256>>>();
    k_prepB<<<(NN * GG + 255) / 256, 256>>>(W1);
    k_gemm1_mma<<<dim3(NN / 128, TT), 256>>>(x_nodes);

    k_count<<<(TT * EE + 255) / 256, 256>>>(ei32);
    k_scan<<<TT, NN>>>();
    k_fill<<<(TT * EE + 255) / 256, 256>>>(ei32);

    k_mp<<<dim3(NN, TT), 128>>>(b1, 1);
    k_gemm2<<<dim3(NN / 128, TT), 256>>>(W2);
    k_mp<<<dim3(NN, TT), 128>>>(b2, 0);
    k_fc<<<NN, 224>>>(Wfc);
    k_pre<<<(TT * 4 * HH + 255) / 256, 256>>>(input, bfc,
                                              Wii, Wgi, bi,
                                              Wif, Wgf, bf,
                                              Wig, Wgg, bg,
                                              Wio, Wgo, bo);
    k_lstm<<<LSTM_NB, 256>>>(Whi, Whf, Whg, Who, out);

    (void)in_sizes; (void)n_in; (void)out_size;
}

// round 15
// speedup vs baseline: 1.0634x; 1.0634x over previous
#include <cuda_runtime.h>
#include <cuda_bf16.h>
#include <math.h>
#include <stdint.h>

#define TT 96
#define NN 1024
#define GG 128
#define HH 512
#define EE 32768
#define INW 64
#define DD2 56

typedef unsigned long long ull;

// ---------------- scratch (static __device__, no allocs) ----------------
__device__ float d_bufA[TT * NN * GG];   // gemm outputs
__device__ float d_bufB[TT * NN * GG];   // mp outputs
__device__ int   d_cnt[TT * NN];
__device__ int   d_offs[TT * NN];
__device__ int   d_cursor[TT * NN];
__device__ float d_dinv[TT * NN];
__device__ int   d_csr[TT * EE];
__device__ float d_gacc[TT * DD2];
__device__ float d_pre[TT * 4 * HH];
__device__ float d_hbuf[2 * HH];
__device__ float d_cbuf[HH];
__device__ unsigned d_bar;
__device__ int   d_eistride;
// W1 split to bf16 hi/lo, packed per 32-K chunk as [kc][n][kk] (n=0..127, kk=0..31)
__device__ __nv_bfloat16 d_W1h[NN * GG];
__device__ __nv_bfloat16 d_W1l[NN * GG];

// ---------------- f32x2 helpers (packed fp32 FMA pipe) ----------------
__device__ __forceinline__ ull f32x2_fma(ull a, ull b, ull c) {
    ull d;
    asm("fma.rn.f32x2 %0, %1, %2, %3;" : "=l"(d) : "l"(a), "l"(b), "l"(c));
    return d;
}
__device__ __forceinline__ ull f32x2_dup(float x) {
    ull d;
    asm("mov.b64 %0, {%1, %1};" : "=l"(d) : "f"(x));
    return d;
}
__device__ __forceinline__ float2 f32x2_unpack(ull v) {
    float2 r;
    asm("mov.b64 {%0, %1}, %2;" : "=f"(r.x), "=f"(r.y) : "l"(v));
    return r;
}

// ---------------- mma.sync bf16 (baseline PTX, HMMA path) -----------------
__device__ __forceinline__ void mma16816(float* d, const uint32_t* a,
                                         uint32_t b0, uint32_t b1) {
    asm volatile(
        "mma.sync.aligned.m16n8k16.row.col.f32.bf16.bf16.f32 "
        "{%0,%1,%2,%3}, {%4,%5,%6,%7}, {%8,%9}, {%0,%1,%2,%3};"
        : "+f"(d[0]), "+f"(d[1]), "+f"(d[2]), "+f"(d[3])
        : "r"(a[0]), "r"(a[1]), "r"(a[2]), "r"(a[3]), "r"(b0), "r"(b1));
}

// ---------------- edge_index dtype detection ------------------------------
__global__ void k_detect(const int* __restrict__ ei32) {
    __shared__ int any;
    if (threadIdx.x == 0) any = 0;
    __syncthreads();
    int v = ei32[2 * threadIdx.x + 1] | ei32[2 * (threadIdx.x + 4096) + 1];
    if (v != 0) atomicOr(&any, 1);
    __syncthreads();
    if (threadIdx.x == 0) d_eistride = any ? 1 : 2;
}

// ---------------- init ----------------
__global__ void k_init() {
    int i = blockIdx.x * blockDim.x + threadIdx.x;
    if (i < TT * NN) d_cnt[i] = 0;
    if (i < TT * DD2) d_gacc[i] = 0.f;
    if (i < 2 * HH) d_hbuf[i] = 0.f;
    if (i < HH) d_cbuf[i] = 0.f;
    if (i == 0) d_bar = 0u;
}

// ---------------- W1 -> bf16 hi/lo chunk-packed [kc][n][kk] ---------------
__global__ void k_prepB(const float* __restrict__ W1) {
    int idx = blockIdx.x * blockDim.x + threadIdx.x;   // 1024*128
    if (idx >= NN * GG) return;
    int k = idx >> 7;       // 0..1023
    int n = idx & 127;
    float w = W1[idx];
    __nv_bfloat16 h = __float2bfloat16(w);
    __nv_bfloat16 l = __float2bfloat16(w - __bfloat162float(h));
    int kc = k >> 5, kk = k & 31;
    int off = kc * 4096 + n * 32 + kk;
    d_W1h[off] = h;
    d_W1l[off] = l;
}

// ---------------- GEMM1 via mma.sync bf16-split ---------------------------
// bufA[t][128-tile] = x_nodes[t] @ W1 ; 8 warps, warp tile 32x64, K chunk 32.
// __launch_bounds__(256,2): cap regs at 128 so 2 CTAs/SM co-reside
// (4 warps/SMSP doubles latency-hiding vs the measured occ=12.5% @142 regs).
__global__ void __launch_bounds__(256, 2)
k_gemm1_mma(const float* __restrict__ A) {
    __shared__ __nv_bfloat16 sAh[128][36], sAl[128][36];
    __shared__ __nv_bfloat16 sBh[128][36], sBl[128][36];
    int t = blockIdx.y, m0 = blockIdx.x * 128;
    const float* At = A + (size_t)t * NN * NN + (size_t)m0 * NN;
    float* Ct = d_bufA + (size_t)t * NN * GG + (size_t)m0 * GG;
    int tid = threadIdx.x, wid = tid >> 5, lane = tid & 31;
    int wm = (wid >> 1) * 32, wn = (wid & 1) * 64;
    int lr = lane >> 2, lc = (lane & 3) * 2;

    float acc[2][8][4];
#pragma unroll
    for (int mt = 0; mt < 2; mt++)
#pragma unroll
        for (int nt = 0; nt < 8; nt++)
#pragma unroll
            for (int q = 0; q < 4; q++) acc[mt][nt][q] = 0.f;

#pragma unroll 1
    for (int kc = 0; kc < 32; kc++) {
        __syncthreads();
        // A chunk: 128 rows x 32 k fp32 -> bf16 hi/lo (2048 float2, 8/thread)
#pragma unroll
        for (int i = 0; i < 8; i++) {
            int lin = tid + i * 256;
            int m = lin >> 4, kp = lin & 15;
            float2 v = *(const float2*)&At[(size_t)m * NN + kc * 32 + kp * 2];
            __nv_bfloat16 h0 = __float2bfloat16(v.x);
            __nv_bfloat16 h1 = __float2bfloat16(v.y);
            __nv_bfloat16 l0 = __float2bfloat16(v.x - __bfloat162float(h0));
            __nv_bfloat16 l1 = __float2bfloat16(v.y - __bfloat162float(h1));
            __nv_bfloat162 hh; hh.x = h0; hh.y = h1;
            __nv_bfloat162 ll; ll.x = l0; ll.y = l1;
            *(__nv_bfloat162*)&sAh[m][kp * 2] = hh;
            *(__nv_bfloat162*)&sAl[m][kp * 2] = ll;
        }
        // B chunk: copy chunk-packed [n][kk] hi/lo images (uint32 = 2 bf16)
        {
            const uint32_t* gh = (const uint32_t*)d_W1h + kc * 2048;
            const uint32_t* gl = (const uint32_t*)d_W1l + kc * 2048;
#pragma unroll
            for (int i = 0; i < 8; i++) {
                int lin = tid + i * 256;
                int n = lin >> 4, kp = lin & 15;
                *(uint32_t*)&sBh[n][kp * 2] = gh[lin];
                *(uint32_t*)&sBl[n][kp * 2] = gl[lin];
            }
        }
        __syncthreads();
#pragma unroll
        for (int ks = 0; ks < 2; ks++) {
            int kb = ks * 16;
            uint32_t ah[2][4], al[2][4];
#pragma unroll
            for (int mt = 0; mt < 2; mt++) {
                int r0 = wm + mt * 16 + lr;
                ah[mt][0] = *(uint32_t*)&sAh[r0][kb + lc];
                ah[mt][1] = *(uint32_t*)&sAh[r0 + 8][kb + lc];
                ah[mt][2] = *(uint32_t*)&sAh[r0][kb + lc + 8];
                ah[mt][3] = *(uint32_t*)&sAh[r0 + 8][kb + lc + 8];
                al[mt][0] = *(uint32_t*)&sAl[r0][kb + lc];
                al[mt][1] = *(uint32_t*)&sAl[r0 + 8][kb + lc];
                al[mt][2] = *(uint32_t*)&sAl[r0][kb + lc + 8];
                al[mt][3] = *(uint32_t*)&sAl[r0 + 8][kb + lc + 8];
            }
#pragma unroll
            for (int nt = 0; nt < 8; nt++) {
                int c0 = wn + nt * 8 + lr;
                uint32_t bh0 = *(uint32_t*)&sBh[c0][kb + lc];
                uint32_t bh1 = *(uint32_t*)&sBh[c0][kb + lc + 8];
                uint32_t bl0 = *(uint32_t*)&sBl[c0][kb + lc];
                uint32_t bl1 = *(uint32_t*)&sBl[c0][kb + lc + 8];
#pragma unroll
                for (int mt = 0; mt < 2; mt++) {
                    mma16816(acc[mt][nt], ah[mt], bh0, bh1);
                    mma16816(acc[mt][nt], ah[mt], bl0, bl1);
                    mma16816(acc[mt][nt], al[mt], bh0, bh1);
                }
            }
        }
    }
#pragma unroll
    for (int mt = 0; mt < 2; mt++)
#pragma unroll
        for (int nt = 0; nt < 8; nt++) {
            int r = wm + mt * 16 + lr;
            int c = wn + nt * 8 + lc;
            Ct[(size_t)r * GG + c]       = acc[mt][nt][0];
            Ct[(size_t)r * GG + c + 1]   = acc[mt][nt][1];
            Ct[(size_t)(r + 8) * GG + c]     = acc[mt][nt][2];
            Ct[(size_t)(r + 8) * GG + c + 1] = acc[mt][nt][3];
        }
}

// ---------------- degree count ----------------
__global__ void k_count(const int* __restrict__ ei32) {
    int idx = blockIdx.x * blockDim.x + threadIdx.x;
    if (idx >= TT * EE) return;
    int t = idx / EE, e = idx - t * EE;
    int st = d_eistride;
    size_t k = (size_t)t * 2 * EE + EE + e;
    int dst = ei32[k * st] & (NN - 1);
    atomicAdd(&d_cnt[t * NN + dst], 1);
}

// ---------------- per-t exclusive scan + dinv ----------------
__global__ void k_scan() {
    __shared__ int s[2][NN];
    int t = blockIdx.x, n = threadIdx.x;
    int c = d_cnt[t * NN + n];
    d_dinv[t * NN + n] = rsqrtf((float)(c + 1));
    s[0][n] = c;
    __syncthreads();
    int p = 0;
    for (int off = 1; off < NN; off <<= 1) {
        int v = s[p][n] + ((n >= off) ? s[p][n - off] : 0);
        s[1 - p][n] = v;
        __syncthreads();
        p = 1 - p;
    }
    int excl = s[p][n] - c;
    d_offs[t * NN + n] = excl;
    d_cursor[t * NN + n] = excl;
}

// ---------------- CSR fill ----------------
__global__ void k_fill(const int* __restrict__ ei32) {
    int idx = blockIdx.x * blockDim.x + threadIdx.x;
    if (idx >= TT * EE) return;
    int t = idx / EE, e = idx - t * EE;
    int st = d_eistride;
    size_t ksrc = (size_t)t * 2 * EE + e;
    size_t kdst = ksrc + EE;
    int src = ei32[ksrc * st] & (NN - 1);
    int dst = ei32[kdst * st] & (NN - 1);
    int pos = atomicAdd(&d_cursor[t * NN + dst], 1);
    d_csr[(size_t)t * EE + pos] = src;
}

// ---------------- SGEMM2 (f32x2): bufA[t] = bufB[t](1024x128) @ W2 --------
__global__ void __launch_bounds__(256)
k_gemm2(const float* __restrict__ B) {
    int t = blockIdx.y;
    int m0 = blockIdx.x * 128;
    const float* At = d_bufB + (size_t)t * NN * GG;
    float* Ct = d_bufA + (size_t)t * NN * GG;

    __shared__ float As[8][128];
    __shared__ float Bs[8][128];

    int tid = threadIdx.x;
    int tx = tid & 15, ty = tid >> 4;
    int am = tid >> 1, ap = (tid & 1) * 4;
    int brow = tid >> 5, bcol = (tid & 31) * 4;

    ull acc[8][4];
#pragma unroll
    for (int r = 0; r < 8; r++)
#pragma unroll
        for (int q = 0; q < 4; q++) acc[r][q] = 0ull;

    for (int k0 = 0; k0 < 128; k0 += 8) {
        float4 av = *(const float4*)&At[(size_t)(m0 + am) * 128 + k0 + ap];
        float4 bv = *(const float4*)&B[(size_t)(k0 + brow) * 128 + bcol];
        __syncthreads();
        As[ap + 0][am] = av.x; As[ap + 1][am] = av.y;
        As[ap + 2][am] = av.z; As[ap + 3][am] = av.w;
        Bs[brow][bcol + 0] = bv.x; Bs[brow][bcol + 1] = bv.y;
        Bs[brow][bcol + 2] = bv.z; Bs[brow][bcol + 3] = bv.w;
        __syncthreads();
#pragma unroll
        for (int kk = 0; kk < 8; kk++) {
            float4 b0 = *(float4*)&Bs[kk][tx * 4];
            float4 b1 = *(float4*)&Bs[kk][64 + tx * 4];
            ull bp0 = ((ull*)&b0)[0], bp1 = ((ull*)&b0)[1];
            ull bp2 = ((ull*)&b1)[0], bp3 = ((ull*)&b1)[1];
            float ar[8];
#pragma unroll
            for (int u = 0; u < 4; u++) {
                ar[u] = As[kk][ty * 4 + u];
                ar[4 + u] = As[kk][64 + ty * 4 + u];
            }
#pragma unroll
            for (int r = 0; r < 8; r++) {
                ull da = f32x2_dup(ar[r]);
                acc[r][0] = f32x2_fma(da, bp0, acc[r][0]);
                acc[r][1] = f32x2_fma(da, bp1, acc[r][1]);
                acc[r][2] = f32x2_fma(da, bp2, acc[r][2]);
                acc[r][3] = f32x2_fma(da, bp3, acc[r][3]);
            }
        }
    }
#pragma unroll
    for (int r = 0; r < 8; r++) {
        int row = m0 + ((r < 4) ? (ty * 4 + r) : (64 + ty * 4 + (r - 4)));
        float2 c0 = f32x2_unpack(acc[r][0]);
        float2 c1 = f32x2_unpack(acc[r][1]);
        float2 c2 = f32x2_unpack(acc[r][2]);
        float2 c3 = f32x2_unpack(acc[r][3]);
        float4 o0 = make_float4(c0.x, c0.y, c1.x, c1.y);
        float4 o1 = make_float4(c2.x, c2.y, c3.x, c3.y);
        *(float4*)&Ct[(size_t)row * GG + tx * 4] = o0;
        *(float4*)&Ct[(size_t)row * GG + 64 + tx * 4] = o1;
    }
}

// ---------------- message passing (CSR gather): bufA -> bufB -------------
__global__ void k_mp(const float* __restrict__ bias, int relu) {
    int t = blockIdx.y, n = blockIdx.x, f = threadIdx.x;
    const float* xwt = d_bufA + (size_t)t * NN * GG;
    float dn = d_dinv[t * NN + n];
    float acc = bias[f] + dn * dn * xwt[(size_t)n * GG + f];
    int s = d_offs[t * NN + n];
    int c = d_cnt[t * NN + n];
    const int* csr = d_csr + (size_t)t * EE + s;

    __shared__ int ssrc[128];
    __shared__ float snrm[128];

    for (int base = 0; base < c; base += 128) {
        int m = c - base; if (m > 128) m = 128;
        __syncthreads();
        if (f < m) {
            int sr = csr[base + f];
            ssrc[f] = sr;
            snrm[f] = dn * d_dinv[t * NN + sr];
        }
        __syncthreads();
        float a0 = 0.f, a1 = 0.f, a2 = 0.f, a3 = 0.f;
        float a4 = 0.f, a5 = 0.f, a6 = 0.f, a7 = 0.f;
        int i = 0;
        for (; i + 8 <= m; i += 8) {
            a0 += snrm[i + 0] * xwt[(size_t)ssrc[i + 0] * GG + f];
            a1 += snrm[i + 1] * xwt[(size_t)ssrc[i + 1] * GG + f];
            a2 += snrm[i + 2] * xwt[(size_t)ssrc[i + 2] * GG + f];
            a3 += snrm[i + 3] * xwt[(size_t)ssrc[i + 3] * GG + f];
            a4 += snrm[i + 4] * xwt[(size_t)ssrc[i + 4] * GG + f];
            a5 += snrm[i + 5] * xwt[(size_t)ssrc[i + 5] * GG + f];
            a6 += snrm[i + 6] * xwt[(size_t)ssrc[i + 6] * GG + f];
            a7 += snrm[i + 7] * xwt[(size_t)ssrc[i + 7] * GG + f];
        }
        for (; i < m; i++)
            a0 += snrm[i] * xwt[(size_t)ssrc[i] * GG + f];
        acc += ((a0 + a1) + (a2 + a3)) + ((a4 + a5) + (a6 + a7));
    }
    if (relu) acc = fmaxf(acc, 0.f);
    d_bufB[(size_t)t * NN * GG + (size_t)n * GG + f] = acc;
}

// ---------------- FC: gacc[t][:] += bufB[t][n][:] @ Wfc[n-chunk] ----------
__global__ void k_fc(const float* __restrict__ Wfc) {
    __shared__ float Ws[128 * DD2];
    __shared__ float xs[128];
    __shared__ float ps[224];
    int n = blockIdx.x;
    int tid = threadIdx.x;
    for (int i = tid; i < 128 * DD2; i += 224)
        Ws[i] = Wfc[(size_t)n * 128 * DD2 + i];
    int dd = tid % DD2, q = tid / DD2;
    for (int t = 0; t < TT; t++) {
        __syncthreads();
        if (tid < 128)
            xs[tid] = d_bufB[(size_t)t * NN * GG + (size_t)n * GG + tid];
        __syncthreads();
        float a = 0.f;
#pragma unroll 8
        for (int k = q * 32; k < q * 32 + 32; k++)
            a += xs[k] * Ws[k * DD2 + dd];
        ps[tid] = a;
        __syncthreads();
        if (q == 0) {
            float ssum = a + ps[56 + dd] + ps[112 + dd] + ps[168 + dd];
            atomicAdd(&d_gacc[t * DD2 + dd], ssum);
        }
    }
}

// ---------------- pre-activations: x@W_i + relu(g)@W_g + b ----------------
__global__ void k_pre(const float* __restrict__ input,
                      const float* __restrict__ bfc,
                      const float* __restrict__ Wii, const float* __restrict__ Wgi, const float* __restrict__ bi,
                      const float* __restrict__ Wif, const float* __restrict__ Wgf, const float* __restrict__ bf,
                      const float* __restrict__ Wig, const float* __restrict__ Wgg, const float* __restrict__ bg,
                      const float* __restrict__ Wio, const float* __restrict__ Wgo, const float* __restrict__ bo) {
    int idx = blockIdx.x * blockDim.x + threadIdx.x;
    if (idx >= TT * 4 * HH) return;
    int t = idx >> 11;
    int r = idx & 2047;
    int gate = r >> 9;
    int hh = r & 511;
    const float* Wi = (gate == 0) ? Wii : (gate == 1) ? Wif : (gate == 2) ? Wig : Wio;
    const float* Wg = (gate == 0) ? Wgi : (gate == 1) ? Wgf : (gate == 2) ? Wgg : Wgo;
    const float* bb = (gate == 0) ? bi : (gate == 1) ? bf : (gate == 2) ? bg : bo;
    const float* x = input + (size_t)t * INW;
    float a = bb[hh];
#pragma unroll 8
    for (int k = 0; k < INW; k++)
        a += x[k] * Wi[(size_t)k * HH + hh];
#pragma unroll 8
    for (int d = 0; d < DD2; d++) {
        float gd = d_gacc[t * DD2 + d] + bfc[d];
        gd = fmaxf(gd, 0.f);
        a += gd * Wg[(size_t)d * HH + hh];
    }
    d_pre[(size_t)t * 2048 + gate * 512 + hh] = a;
}

// ---------------- persistent LSTM recurrence ----------------
#define LSTM_NB 64
__global__ void __launch_bounds__(256, 1)
k_lstm(const float* __restrict__ Whi, const float* __restrict__ Whf,
       const float* __restrict__ Whg, const float* __restrict__ Who,
       float* __restrict__ out) {
    int wid = (blockIdx.x * 256 + threadIdx.x) >> 5;
    int lane = threadIdx.x & 31;
    int j = wid;

    float wi[16], wf[16], wg[16], wo[16];
#pragma unroll
    for (int q = 0; q < 16; q++) {
        int m = lane * 16 + q;
        wi[q] = Whi[(size_t)m * HH + j];
        wf[q] = Whf[(size_t)m * HH + j];
        wg[q] = Whg[(size_t)m * HH + j];
        wo[q] = Who[(size_t)m * HH + j];
    }

    float c = 0.f, h = 0.f;
    for (int t = 0; t < TT; t++) {
        volatile float* hb = d_hbuf + (t & 1) * HH;
        float ai = 0.f, af = 0.f, ag = 0.f, ao = 0.f;
#pragma unroll
        for (int q = 0; q < 16; q++) {
            float hv = hb[lane * 16 + q];
            ai += wi[q] * hv;
            af += wf[q] * hv;
            ag += wg[q] * hv;
            ao += wo[q] * hv;
        }
#pragma unroll
        for (int off = 16; off > 0; off >>= 1) {
            ai += __shfl_xor_sync(0xffffffffu, ai, off);
            af += __shfl_xor_sync(0xffffffffu, af, off);
            ag += __shfl_xor_sync(0xffffffffu, ag, off);
            ao += __shfl_xor_sync(0xffffffffu, ao, off);
        }
        if (lane == 0) {
            const float* p = d_pre + (size_t)t * 2048;
            float xi = p[j] + ai;
            float xf = p[512 + j] + af;
            float xg = p[1024 + j] + ag;
            float xo = p[1536 + j] + ao;
            float ii = 1.f / (1.f + expf(-xi));
            float ff = 1.f / (1.f + expf(-xf));
            float gg = tanhf(xg);
            float oo = 1.f / (1.f + expf(-xo));
            c = ff * c + ii * gg;
            h = oo * tanhf(c);
            d_hbuf[((t + 1) & 1) * HH + j] = h;
            out[(size_t)t * HH + j] = h;
        }
        __threadfence();
        __syncthreads();
        if (threadIdx.x == 0) {
            atomicAdd(&d_bar, 1u);
            unsigned target = (unsigned)LSTM_NB * (unsigned)(t + 1);
            while (*((volatile unsigned*)&d_bar) < target) {}
        }
        __syncthreads();
        __threadfence();
    }
    if (lane == 0) {
        out[(size_t)TT * HH + j] = h;
        out[(size_t)TT * HH + HH + j] = c;
    }
}

// ---------------- launch ----------------
extern "C" void kernel_launch(void* const* d_in, const int* in_sizes, int n_in,
                              void* d_out, int out_size) {
    const float* input    = (const float*)d_in[0];
    const float* x_nodes  = (const float*)d_in[1];
    const int*   ei32     = (const int*)d_in[2];
    const float* W1  = (const float*)d_in[3];
    const float* b1  = (const float*)d_in[4];
    const float* W2  = (const float*)d_in[5];
    const float* b2  = (const float*)d_in[6];
    const float* Wfc = (const float*)d_in[7];
    const float* bfc = (const float*)d_in[8];
    const float* Wii = (const float*)d_in[9];
    const float* Wgi = (const float*)d_in[10];
    const float* Whi = (const float*)d_in[11];
    const float* bi  = (const float*)d_in[12];
    const float* Wif = (const float*)d_in[13];
    const float* Wgf = (const float*)d_in[14];
    const float* Whf = (const float*)d_in[15];
    const float* bf  = (const float*)d_in[16];
    const float* Wig = (const float*)d_in[17];
    const float* Wgg = (const float*)d_in[18];
    const float* Whg = (const float*)d_in[19];
    const float* bg  = (const float*)d_in[20];
    const float* Wio = (const float*)d_in[21];
    const float* Wgo = (const float*)d_in[22];
    const float* Who = (const float*)d_in[23];
    const float* bo  = (const float*)d_in[24];
    float* out = (float*)d_out;

    // order: k_gemm1_mma is the 4th launch (ncu profiling window)
    k_detect<<<1, 256>>>(ei32);
    k_init<<<(TT * NN + 255) / 256, 256>>>();
    k_prepB<<<(NN * GG + 255) / 256, 256>>>(W1);
    k_gemm1_mma<<<dim3(NN / 128, TT), 256>>>(x_nodes);

    k_count<<<(TT * EE + 255) / 256, 256>>>(ei32);
    k_scan<<<TT, NN>>>();
    k_fill<<<(TT * EE + 255) / 256, 256>>>(ei32);

    k_mp<<<dim3(NN, TT), 128>>>(b1, 1);
    k_gemm2<<<dim3(NN / 128, TT), 256>>>(W2);
    k_mp<<<dim3(NN, TT), 128>>>(b2, 0);
    k_fc<<<NN, 224>>>(Wfc);
    k_pre<<<(TT * 4 * HH + 255) / 256, 256>>>(input, bfc,
                                              Wii, Wgi, bi,
                                              Wif, Wgf, bf,
                                              Wig, Wgg, bg,
                                              Wio, Wgo, bo);
    k_lstm<<<LSTM_NB, 256>>>(Whi, Whf, Whg, Who, out);

    (void)in_sizes; (void)n_in; (void)out_size;
}